// round 3
// baseline (speedup 1.0000x reference)
#include <cuda_runtime.h>
#include <cuda_bf16.h>
#include <math.h>

#define NSAMP 64
#define TLEN  512
#define DDIM  16
#define NDIAG 1023
#define BIGL  1.0e10f
#define LOG2E 1.4426950408889634f
#define LN2   0.6931471805599453f

// Scratch: D (pre-scaled by log2e) in diagonal-major layout: g_Ddiag[n][kk][ii]
__device__ float g_Ddiag[(size_t)NSAMP * 1024 * 512];   // 134 MB
__device__ float g_res[NSAMP];

__device__ __forceinline__ float ex2f(float x){ float y; asm("ex2.approx.ftz.f32 %0, %1;" : "=f"(y) : "f"(x)); return y; }
__device__ __forceinline__ float lg2f(float x){ float y; asm("lg2.approx.ftz.f32 %0, %1;" : "=f"(y) : "f"(x)); return y; }

// ---------------------------------------------------------------------------
// Kernel A: D[n,ii,jj] = ||X[n,ii]-Z[jj]||^2 * log2e, stored DIAGONAL-major.
// 32-row tiles, 256 threads, ~105KB smem -> 2 blocks/SM.
// ---------------------------------------------------------------------------
__global__ void __launch_bounds__(256) compute_D_kernel(const float* __restrict__ X,
                                                        const float* __restrict__ Z)
{
    extern __shared__ float sm[];
    float* ts  = sm;                         // 32*514
    float* zsh = ts  + 32 * 514;             // 512*17
    float* z2s = zsh + 512 * 17;             // 512
    float* xs  = z2s + 512;                  // 32*16

    const int n    = blockIdx.y;
    const int row0 = blockIdx.x * 32;
    const int tid  = threadIdx.x;
    const int w    = tid >> 5;
    const int lane = tid & 31;

    for (int i = tid; i < 512 * 16; i += 256)
        zsh[(i >> 4) * 17 + (i & 15)] = Z[i];
    const float* Xn = X + ((size_t)n * TLEN + row0) * DDIM;
    for (int i = tid; i < 32 * 16; i += 256)
        xs[i] = Xn[i];
    __syncthreads();

    for (int r = tid; r < 512; r += 256) {
        float s = 0.f;
        #pragma unroll
        for (int c = 0; c < 16; c++) { float v = zsh[r * 17 + c]; s = fmaf(v, v, s); }
        z2s[r] = s;
    }

    float xr[4][16], x2r[4];
    #pragma unroll
    for (int q = 0; q < 4; q++) {
        float s = 0.f;
        #pragma unroll
        for (int c = 0; c < 16; c++) {
            float v = xs[(w * 4 + q) * 16 + c];
            xr[q][c] = v; s = fmaf(v, v, s);
        }
        x2r[q] = s;
    }
    __syncthreads();

    #pragma unroll 1
    for (int t = 0; t < 16; t++) {
        const int jj = lane + 32 * t;
        float zr[16];
        #pragma unroll
        for (int c = 0; c < 16; c++) zr[c] = zsh[jj * 17 + c];
        const float z2v = z2s[jj];
        #pragma unroll
        for (int q = 0; q < 4; q++) {
            float acc = 0.f;
            #pragma unroll
            for (int c = 0; c < 16; c++) acc = fmaf(xr[q][c], zr[c], acc);
            float dv = fmaf(acc, -2.0f, x2r[q] + z2v);
            ts[(w * 4 + q) * 514 + jj] = fmaxf(dv, 0.0f) * LOG2E;
        }
    }
    __syncthreads();

    // Diagonal-major write-out: diagonals kk in [row0, row0+542]
    const size_t base = (size_t)n * (1024 * 512);
    for (int kkoff = w; kkoff < 543; kkoff += 8) {
        const int kk   = row0 + kkoff;
        const int iilo = max(row0, kk - 511);
        const int iihi = min(row0 + 31, kk);
        for (int ii = iilo + lane; ii <= iihi; ii += 32)
            g_Ddiag[base + (size_t)kk * 512 + ii] = ts[(ii - row0) * 514 + (kk - ii)];
    }
}

// ---------------------------------------------------------------------------
// Kernel B: log2-domain soft-DTW wavefront, LOCK-FREE warp chain.
// Warp w depends only on warp w-1 one iteration back: boundary values go in a
// full smem array (no back-pressure), progress via release/acquire flags.
// No __syncthreads in the main loop.
// ---------------------------------------------------------------------------
#define PF 8

__global__ void __launch_bounds__(512) dp_kernel()
{
    extern __shared__ float sb[];            // [16][1024] boundary values
    __shared__ int sflag[16];                // last iter published by warp w

    const int n    = blockIdx.x;
    const int tid  = threadIdx.x;
    const int w    = tid >> 5;
    const int lane = tid & 31;

    if (tid < 16) sflag[tid] = -1;

    float r_cur  = BIGL;                     // diag k-1 value (log2 units)
    float r_diag = (tid == 0) ? 0.0f : BIGL; // corner R[0][0] = 0

    const float* __restrict__ Dn = g_Ddiag + (size_t)n * (1024 * 512);
    float dbuf[PF];
    #pragma unroll
    for (int i = 0; i < PF; i++) dbuf[i] = Dn[(size_t)i * 512 + tid];

    float* myrow  = sb + w * 1024;
    float* prow   = sb + (w > 0 ? w - 1 : 0) * 1024;
    int*   myflag = &sflag[w];
    int*   pflag  = &sflag[w > 0 ? w - 1 : 0];
    const unsigned myflag_s = (unsigned)__cvta_generic_to_shared(myflag);
    const unsigned pflag_s  = (unsigned)__cvta_generic_to_shared(pflag);
    int ready = -1;

    __syncthreads();                         // flags + initial state visible

    for (int kk = 0; kk < NDIAG; ++kk) {
        // off-chain prework on (left, dia)
        const float pre_m = fminf(r_cur, r_diag);
        const float pre_M = fmaxf(r_cur, r_diag);
        const float pre_s = r_cur + r_diag;
        const float dplus = dbuf[kk & (PF - 1)];

        float up = __shfl_up_sync(0xffffffffu, r_cur, 1);
        if (lane == 0) {
            if (w == 0 || kk == 0) {
                up = BIGL;
            } else {
                if (ready < kk - 1) {
                    do {
                        asm volatile("ld.acquire.cta.shared.b32 %0, [%1];"
                                     : "=r"(ready) : "r"(pflag_s) : "memory");
                    } while (ready < kk - 1);
                }
                up = prow[kk - 1];
            }
        }

        const float m   = fminf(pre_m, up);
        const float Mx  = fmaxf(pre_M, up);
        const float mid = (pre_s + up) - m - Mx;
        const float s   = 1.0f + ex2f(m - mid) + ex2f(m - Mx);
        float v = (dplus + m) - lg2f(s);
        if ((unsigned)(kk - tid) >= 512u) v = BIGL;      // outside DP band

        r_diag = up;
        r_cur  = v;
        if (lane == 31) {
            myrow[kk] = v;                               // plain STS
            asm volatile("st.release.cta.shared.b32 [%0], %1;"
                         :: "r"(myflag_s), "r"(kk) : "memory");
        }

        if (kk + PF < NDIAG) dbuf[kk & (PF - 1)] = Dn[(size_t)(kk + PF) * 512 + tid];
    }

    if (tid == TLEN - 1) g_res[n] = r_cur * LN2;         // back to natural log units
}

// ---------------------------------------------------------------------------
// Kernel C: deterministic weighted reduction.
// ---------------------------------------------------------------------------
__global__ void reduce_kernel(const float* __restrict__ wts, float* __restrict__ out)
{
    __shared__ float s[64];
    const int tid = threadIdx.x;
    s[tid] = g_res[tid] * wts[tid];
    __syncthreads();
    #pragma unroll
    for (int off = 32; off > 0; off >>= 1) {
        if (tid < off) s[tid] += s[tid + off];
        __syncthreads();
    }
    if (tid == 0) out[0] = s[0];
}

// ---------------------------------------------------------------------------
extern "C" void kernel_launch(void* const* d_in, const int* in_sizes, int n_in,
                              void* d_out, int out_size)
{
    const float* X = nullptr; const float* wts = nullptr; const float* Z = nullptr;
    for (int i = 0; i < n_in; i++) {
        if      (in_sizes[i] == NSAMP)        wts = (const float*)d_in[i];
        else if (in_sizes[i] == TLEN * DDIM)  Z   = (const float*)d_in[i];
        else                                  X   = (const float*)d_in[i];
    }
    float* out = (float*)d_out;

    const int smemA = (32 * 514 + 512 * 17 + 512 + 32 * 16) * (int)sizeof(float); // 104704
    cudaFuncSetAttribute(compute_D_kernel, cudaFuncAttributeMaxDynamicSharedMemorySize, smemA);
    const int smemB = 16 * 1024 * (int)sizeof(float);                              // 65536
    cudaFuncSetAttribute(dp_kernel, cudaFuncAttributeMaxDynamicSharedMemorySize, smemB);

    compute_D_kernel<<<dim3(16, NSAMP), 256, smemA>>>(X, Z);
    dp_kernel<<<NSAMP, 512, smemB>>>();
    reduce_kernel<<<1, 64>>>(wts, out);
}